// round 11
// baseline (speedup 1.0000x reference)
#include <cuda_runtime.h>
#include <cuda_fp16.h>
#include <stdint.h>

// DCT-III along channels via mma.sync m16n8k16 fp16 (A fp16, B fp16 single pass).
// out[b,c,p] = sum_k M[c,k] x[b,k,p],  M[c,k] = (k==0)?1:2*cos(pi*k*(2c+1)/512)
// Parity: E[c]=sum_{even k}, O[c]=sum_{odd k}; out[c]=E+O, out[255-c]=E-O.
// Round 11: R6 structure, B split dropped (halves HMMA + B LDS + cvt;
// rel_err ~3.5e-4 predicted), LDG prefetch depth 2 k-steps.

#define C_DIM  256
#define HW     16384
#define NTILES 1024
#define GRID_P 148
#define THREADS 256

#define SMB 65536
#define SMEM_TOTAL 98304   // A 64KB + B double buffer 2x16KB (lo half unused)

// A image: [kt8][t16 16][lane 32][16B] ; t16 = eo*8 + (c>>4)
__device__ __align__(16) unsigned char g_A[65536];

__global__ void precompute_kernel() {
    int t = blockIdx.x * blockDim.x + threadIdx.x;   // 4096 = [kt][t16][lane]
    int kt = t >> 9;
    int t16 = (t >> 5) & 15;
    int lane = t & 31;
    int gid = lane >> 2, tig = lane & 3;
    int eo = t16 >> 3;
    uint32_t w4[4];
#pragma unroll
    for (int w = 0; w < 4; ++w) {
        int m = t16 * 16 + gid + (w & 1) * 8;
        int c = m & 127;
        int kap0 = tig * 2 + (w >> 1) * 8;
        float v2[2];
#pragma unroll
        for (int h = 0; h < 2; ++h) {
            int k = kt * 32 + 2 * (kap0 + h) + eo;
            if (k == 0) v2[h] = 1.0f;
            else {
                int mm = (k * (2 * c + 1)) & 1023;
                v2[h] = 2.0f * cospif((float)mm * (1.0f / 512.0f));
            }
        }
        __half2 h2 = __floats2half2_rn(v2[0], v2[1]);
        w4[w] = *(uint32_t*)&h2;
    }
    *(uint4*)(g_A + (kt * 16 + t16) * 512 + lane * 16) =
        make_uint4(w4[0], w4[1], w4[2], w4[3]);
}

__device__ __forceinline__ void mma16816(float* c,
    uint32_t a0, uint32_t a1, uint32_t a2, uint32_t a3,
    uint32_t b0, uint32_t b1) {
    asm volatile(
        "mma.sync.aligned.m16n8k16.row.col.f32.f16.f16.f32 "
        "{%0,%1,%2,%3}, {%4,%5,%6,%7}, {%8,%9}, {%0,%1,%2,%3};"
        : "+f"(c[0]), "+f"(c[1]), "+f"(c[2]), "+f"(c[3])
        : "r"(a0), "r"(a1), "r"(a2), "r"(a3), "r"(b0), "r"(b1));
}

__global__ __launch_bounds__(THREADS, 1)
void idct_mma_kernel(const float* __restrict__ x, float* __restrict__ out) {
    extern __shared__ char sm[];
    const int tid  = threadIdx.x;
    const int lane = tid & 31;
    const int q    = lane & 3;
    const int frow = lane >> 2;
    const int wid  = tid >> 5;
    const int cg   = wid & 1;    // 64-channel group
    const int pg   = wid >> 1;   // 32-px group (0..3)

    // B producer role
    const int px  = tid & 127;
    const int par = tid >> 7;
    const int g8  = px >> 3;
    const int r   = px & 7;
    const uint32_t psw = (uint32_t)((r & 4) << 2);
    const uint32_t po1 = (uint32_t)(par * 8192 + g8 * 512) + (((uint32_t)(r * 32)) ^ psw);
    const uint32_t po2 = (uint32_t)(par * 8192 + g8 * 512) + (((uint32_t)(r * 32 + 16)) ^ psw);
    // B consumer offset
    const uint32_t bco = (((uint32_t)(frow * 32)) +
                          (((uint32_t)(q * 8)) ^ ((uint32_t)((frow & 4) << 2))));

    int ti = blockIdx.x;

    const float* xpb = x + (size_t)(ti >> 7) * C_DIM * HW + (ti & 127) * 128
                         + (size_t)par * HW + px;
    // prefetch depth 2: v[0] = kt0, v[1] = kt1
    float v[2][16];
#pragma unroll
    for (int i = 0; i < 16; ++i) v[0][i] = xpb[(size_t)(2 * i) * HW];
#pragma unroll
    for (int i = 0; i < 16; ++i) v[1][i] = xpb[(size_t)(32 + 2 * i) * HW];

    // stage A once (64KB)
    {
        const uint4* src = (const uint4*)g_A;
        uint4* dst = (uint4*)sm;
#pragma unroll
        for (int i = 0; i < 16; ++i) dst[tid + 256 * i] = src[tid + 256 * i];
    }

    float acc[4][2][4][4];
#pragma unroll
    for (int a = 0; a < 4; a++)
#pragma unroll
        for (int e = 0; e < 2; e++)
#pragma unroll
            for (int b = 0; b < 4; b++)
#pragma unroll
                for (int j = 0; j < 4; j++) acc[a][e][b][j] = 0.0f;

    while (ti < NTILES) {
        const float* xnb = xpb;   // next-tile base (set at kt==6)

#pragma unroll 1
        for (int kt = 0; kt < 8; ++kt) {
            const int vb = kt & 1;
            const uint32_t buf = (uint32_t)(kt & 1) * 16384;

            // convert v -> fp16 fragment words, STS (single pass, no lo)
            {
                uint32_t hw_[8];
                const int Wa[8] = {0, 8, 2, 10, 4, 12, 6, 14};
#pragma unroll
                for (int w = 0; w < 8; ++w) {
                    int a = Wa[w];
                    __half2 h2 = __floats2half2_rn(v[vb][a], v[vb][a + 1]);
                    hw_[w] = *(uint32_t*)&h2;
                }
                char* bb = sm + SMB + buf;
                *(uint4*)(bb + po1) = make_uint4(hw_[0], hw_[1], hw_[2], hw_[3]);
                *(uint4*)(bb + po2) = make_uint4(hw_[4], hw_[5], hw_[6], hw_[7]);
            }

            // prefetch k-step kt+2 (or next tile's kt0/kt1) into v[vb]
            {
                const float* nb;
                if (kt < 6) {
                    nb = xpb + (size_t)(32 * (kt + 2)) * HW;
                } else {
                    if (kt == 6) {
                        int tn = (ti + GRID_P < NTILES) ? (ti + GRID_P) : ti;
                        xnb = x + (size_t)(tn >> 7) * C_DIM * HW + (tn & 127) * 128
                                + (size_t)par * HW + px;
                        nb = xnb;
                    } else {
                        nb = xnb + (size_t)32 * HW;
                    }
                }
#pragma unroll
                for (int i = 0; i < 16; ++i) v[vb][i] = nb[(size_t)(2 * i) * HW];
            }

            __syncthreads();

            // B fragments (single pass)
            uint2 Bh[2][4];
#pragma unroll
            for (int pr = 0; pr < 2; ++pr)
#pragma unroll
                for (int nt = 0; nt < 4; ++nt) {
                    const char* bb = sm + SMB + buf + pr * 8192 +
                                     (pg * 4 + nt) * 512 + bco;
                    Bh[pr][nt] = *(const uint2*)(bb);
                }

            // A fragments + mma (one per (eo,mt,nt))
#pragma unroll
            for (int eo = 0; eo < 2; ++eo)
#pragma unroll
                for (int mt = 0; mt < 4; ++mt) {
                    uint4 Aw = *(const uint4*)(sm +
                        (kt * 16 + eo * 8 + cg * 4 + mt) * 512 + lane * 16);
#pragma unroll
                    for (int nt = 0; nt < 4; ++nt)
                        mma16816(acc[mt][eo][nt], Aw.x, Aw.y, Aw.z, Aw.w,
                                 Bh[eo][nt].x, Bh[eo][nt].y);
                }
        }

        // ---- epilogue: parity combine in regs, sector-aligned STG ----
        {
            float* ob = out + (size_t)(ti >> 7) * C_DIM * HW + (ti & 127) * 128;
#pragma unroll
            for (int mt = 0; mt < 4; ++mt) {
                int c = cg * 64 + mt * 16 + frow;
#pragma unroll
                for (int nt = 0; nt < 4; ++nt) {
                    int pxo = pg * 32 + nt * 8 + q * 2;
                    float* E = acc[mt][0][nt];
                    float* O = acc[mt][1][nt];
                    *(float2*)&ob[(size_t)c * HW + pxo] =
                        make_float2(E[0] + O[0], E[1] + O[1]);
                    *(float2*)&ob[(size_t)(255 - c) * HW + pxo] =
                        make_float2(E[0] - O[0], E[1] - O[1]);
                    *(float2*)&ob[(size_t)(c + 8) * HW + pxo] =
                        make_float2(E[2] + O[2], E[3] + O[3]);
                    *(float2*)&ob[(size_t)(247 - c) * HW + pxo] =
                        make_float2(E[2] - O[2], E[3] - O[3]);
                    E[0] = E[1] = E[2] = E[3] = 0.0f;
                    O[0] = O[1] = O[2] = O[3] = 0.0f;
                }
            }
        }

        ti += GRID_P;
        xpb = xnb;
    }
}

extern "C" void kernel_launch(void* const* d_in, const int* in_sizes, int n_in,
                              void* d_out, int out_size) {
    const float* x = (const float*)d_in[0];
    float* out = (float*)d_out;

    cudaFuncSetAttribute(idct_mma_kernel,
                         cudaFuncAttributeMaxDynamicSharedMemorySize, SMEM_TOTAL);
    precompute_kernel<<<16, 256>>>();
    idct_mma_kernel<<<GRID_P, THREADS, SMEM_TOTAL>>>(x, out);
}

// round 12
// speedup vs baseline: 1.6261x; 1.6261x over previous
#include <cuda_runtime.h>
#include <cuda_fp16.h>
#include <stdint.h>

// DCT-III along channels via mma.sync m16n8k16 fp16 (A fp16, B fp16 single pass).
// out[b,c,p] = sum_k M[c,k] x[b,k,p],  M[c,k] = (k==0)?1:2*cos(pi*k*(2c+1)/512)
// Parity: E[c]=sum_{even k}, O[c]=sum_{odd k}; out[c]=E+O, out[255-c]=E-O.
// Round 12: BK=64 super-steps (2 k-chunks per barrier -> 4 barriers/tile),
// static v0/v1 prefetch arrays (R11's v[2][16] was dynamically indexed ->
// local memory -> the regression).

#define C_DIM  256
#define HW     16384
#define NTILES 1024
#define GRID_P 148
#define THREADS 256

#define SMB 65536
#define SMEM_TOTAL 131072   // A 64KB + B double buffer 2x32KB

// A image: [kt8][t16 16][lane 32][16B] ; t16 = eo*8 + (c>>4)
__device__ __align__(16) unsigned char g_A[65536];

__global__ void precompute_kernel() {
    int t = blockIdx.x * blockDim.x + threadIdx.x;   // 4096 = [kt][t16][lane]
    int kt = t >> 9;
    int t16 = (t >> 5) & 15;
    int lane = t & 31;
    int gid = lane >> 2, tig = lane & 3;
    int eo = t16 >> 3;
    uint32_t w4[4];
#pragma unroll
    for (int w = 0; w < 4; ++w) {
        int m = t16 * 16 + gid + (w & 1) * 8;
        int c = m & 127;
        int kap0 = tig * 2 + (w >> 1) * 8;
        float v2[2];
#pragma unroll
        for (int h = 0; h < 2; ++h) {
            int k = kt * 32 + 2 * (kap0 + h) + eo;
            if (k == 0) v2[h] = 1.0f;
            else {
                int mm = (k * (2 * c + 1)) & 1023;
                v2[h] = 2.0f * cospif((float)mm * (1.0f / 512.0f));
            }
        }
        __half2 h2 = __floats2half2_rn(v2[0], v2[1]);
        w4[w] = *(uint32_t*)&h2;
    }
    *(uint4*)(g_A + (kt * 16 + t16) * 512 + lane * 16) =
        make_uint4(w4[0], w4[1], w4[2], w4[3]);
}

__device__ __forceinline__ void mma16816(float* c,
    uint32_t a0, uint32_t a1, uint32_t a2, uint32_t a3,
    uint32_t b0, uint32_t b1) {
    asm volatile(
        "mma.sync.aligned.m16n8k16.row.col.f32.f16.f16.f32 "
        "{%0,%1,%2,%3}, {%4,%5,%6,%7}, {%8,%9}, {%0,%1,%2,%3};"
        : "+f"(c[0]), "+f"(c[1]), "+f"(c[2]), "+f"(c[3])
        : "r"(a0), "r"(a1), "r"(a2), "r"(a3), "r"(b0), "r"(b1));
}

__global__ __launch_bounds__(THREADS, 1)
void idct_mma_kernel(const float* __restrict__ x, float* __restrict__ out) {
    extern __shared__ char sm[];
    const int tid  = threadIdx.x;
    const int lane = tid & 31;
    const int q    = lane & 3;
    const int frow = lane >> 2;
    const int wid  = tid >> 5;
    const int cg   = wid & 1;    // 64-channel group
    const int pg   = wid >> 1;   // 32-px group (0..3)

    // B producer role
    const int px  = tid & 127;
    const int par = tid >> 7;
    const int g8  = px >> 3;
    const int r   = px & 7;
    const uint32_t psw = (uint32_t)((r & 4) << 2);
    const uint32_t po1 = (uint32_t)(par * 8192 + g8 * 512) + (((uint32_t)(r * 32)) ^ psw);
    const uint32_t po2 = (uint32_t)(par * 8192 + g8 * 512) + (((uint32_t)(r * 32 + 16)) ^ psw);
    // B consumer offset
    const uint32_t bco = (((uint32_t)(frow * 32)) +
                          (((uint32_t)(q * 8)) ^ ((uint32_t)((frow & 4) << 2))));

    int ti = blockIdx.x;

    const float* xpb = x + (size_t)(ti >> 7) * C_DIM * HW + (ti & 127) * 128
                         + (size_t)par * HW + px;
    float v0[16], v1[16];     // static arrays -> register-resident
#pragma unroll
    for (int i = 0; i < 16; ++i) v0[i] = xpb[(size_t)(2 * i) * HW];
#pragma unroll
    for (int i = 0; i < 16; ++i) v1[i] = xpb[(size_t)(32 + 2 * i) * HW];

    // stage A once (64KB)
    {
        const uint4* src = (const uint4*)g_A;
        uint4* dst = (uint4*)sm;
#pragma unroll
        for (int i = 0; i < 16; ++i) dst[tid + 256 * i] = src[tid + 256 * i];
    }

    float acc[4][2][4][4];
#pragma unroll
    for (int a = 0; a < 4; a++)
#pragma unroll
        for (int e = 0; e < 2; e++)
#pragma unroll
            for (int b = 0; b < 4; b++)
#pragma unroll
                for (int j = 0; j < 4; j++) acc[a][e][b][j] = 0.0f;

    const int Wa[8] = {0, 8, 2, 10, 4, 12, 6, 14};

    while (ti < NTILES) {
        const float* xnb = xpb;   // next-tile base (set at ss==3)

#pragma unroll 1
        for (int ss = 0; ss < 4; ++ss) {
            const uint32_t stg = SMB + (uint32_t)(ss & 1) * 32768;

            // cvt + STS both chunks (single-pass fp16)
            {
                uint32_t hw_[8];
#pragma unroll
                for (int w = 0; w < 8; ++w) {
                    int a = Wa[w];
                    __half2 h2 = __floats2half2_rn(v0[a], v0[a + 1]);
                    hw_[w] = *(uint32_t*)&h2;
                }
                char* bb = sm + stg;
                *(uint4*)(bb + po1) = make_uint4(hw_[0], hw_[1], hw_[2], hw_[3]);
                *(uint4*)(bb + po2) = make_uint4(hw_[4], hw_[5], hw_[6], hw_[7]);
#pragma unroll
                for (int w = 0; w < 8; ++w) {
                    int a = Wa[w];
                    __half2 h2 = __floats2half2_rn(v1[a], v1[a + 1]);
                    hw_[w] = *(uint32_t*)&h2;
                }
                bb = sm + stg + 16384;
                *(uint4*)(bb + po1) = make_uint4(hw_[0], hw_[1], hw_[2], hw_[3]);
                *(uint4*)(bb + po2) = make_uint4(hw_[4], hw_[5], hw_[6], hw_[7]);
            }

            // prefetch next interval (64 k-values) into v0/v1
            {
                const float* nb;
                if (ss < 3) {
                    nb = xpb + (size_t)(64 * (ss + 1)) * HW;
                } else {
                    int tn = (ti + GRID_P < NTILES) ? (ti + GRID_P) : ti;
                    xnb = x + (size_t)(tn >> 7) * C_DIM * HW + (tn & 127) * 128
                            + (size_t)par * HW + px;
                    nb = xnb;
                }
#pragma unroll
                for (int i = 0; i < 16; ++i) v0[i] = nb[(size_t)(2 * i) * HW];
#pragma unroll
                for (int i = 0; i < 16; ++i) v1[i] = nb[(size_t)(32 + 2 * i) * HW];
            }

            __syncthreads();

            // consume chunk 0 then chunk 1 (64 HMMA/warp per barrier)
#pragma unroll
            for (int c01 = 0; c01 < 2; ++c01) {
                uint2 Bh[2][4];
#pragma unroll
                for (int pr = 0; pr < 2; ++pr)
#pragma unroll
                    for (int nt = 0; nt < 4; ++nt) {
                        const char* bb = sm + stg + c01 * 16384 + pr * 8192 +
                                         (pg * 4 + nt) * 512 + bco;
                        Bh[pr][nt] = *(const uint2*)(bb);
                    }
                const int kt = ss * 2 + c01;
#pragma unroll
                for (int eo = 0; eo < 2; ++eo)
#pragma unroll
                    for (int mt = 0; mt < 4; ++mt) {
                        uint4 Aw = *(const uint4*)(sm +
                            (kt * 16 + eo * 8 + cg * 4 + mt) * 512 + lane * 16);
#pragma unroll
                        for (int nt = 0; nt < 4; ++nt)
                            mma16816(acc[mt][eo][nt], Aw.x, Aw.y, Aw.z, Aw.w,
                                     Bh[eo][nt].x, Bh[eo][nt].y);
                    }
            }
        }

        // ---- epilogue: parity combine in regs, sector-aligned STG ----
        {
            float* ob = out + (size_t)(ti >> 7) * C_DIM * HW + (ti & 127) * 128;
#pragma unroll
            for (int mt = 0; mt < 4; ++mt) {
                int c = cg * 64 + mt * 16 + frow;
#pragma unroll
                for (int nt = 0; nt < 4; ++nt) {
                    int pxo = pg * 32 + nt * 8 + q * 2;
                    float* E = acc[mt][0][nt];
                    float* O = acc[mt][1][nt];
                    *(float2*)&ob[(size_t)c * HW + pxo] =
                        make_float2(E[0] + O[0], E[1] + O[1]);
                    *(float2*)&ob[(size_t)(255 - c) * HW + pxo] =
                        make_float2(E[0] - O[0], E[1] - O[1]);
                    *(float2*)&ob[(size_t)(c + 8) * HW + pxo] =
                        make_float2(E[2] + O[2], E[3] + O[3]);
                    *(float2*)&ob[(size_t)(247 - c) * HW + pxo] =
                        make_float2(E[2] - O[2], E[3] - O[3]);
                    E[0] = E[1] = E[2] = E[3] = 0.0f;
                    O[0] = O[1] = O[2] = O[3] = 0.0f;
                }
            }
        }

        ti += GRID_P;
        xpb = xnb;
    }
}

extern "C" void kernel_launch(void* const* d_in, const int* in_sizes, int n_in,
                              void* d_out, int out_size) {
    const float* x = (const float*)d_in[0];
    float* out = (float*)d_out;

    cudaFuncSetAttribute(idct_mma_kernel,
                         cudaFuncAttributeMaxDynamicSharedMemorySize, SMEM_TOTAL);
    precompute_kernel<<<16, 256>>>();
    idct_mma_kernel<<<GRID_P, THREADS, SMEM_TOTAL>>>(x, out);
}

// round 13
// speedup vs baseline: 1.7813x; 1.0955x over previous
#include <cuda_runtime.h>
#include <cuda_fp16.h>
#include <stdint.h>

// DCT-III along channels via mma.sync m16n8k16 fp16 (A fp16, B fp16 single pass).
// out[b,c,p] = sum_k M[c,k] x[b,k,p],  M[c,k] = (k==0)?1:2*cos(pi*k*(2c+1)/512)
// Parity: E[c]=sum_{even k}, O[c]=sum_{odd k}; out[c]=E+O, out[255-c]=E-O.
// Round 13: R12 schedule (BK=64, 4 barriers/tile) at 512 threads / 16 warps
// (4 per SMSP) via halved per-thread acc (64 regs) -> latency hiding.

#define C_DIM  256
#define HW     16384
#define NTILES 1024
#define GRID_P 148
#define THREADS 512

#define SMB 65536
#define SMEM_TOTAL 131072   // A 64KB + B double buffer 2x32KB

// A image: [kt8][t16 16][lane 32][16B] ; t16 = eo*8 + (c>>4)
__device__ __align__(16) unsigned char g_A[65536];

__global__ void precompute_kernel() {
    int t = blockIdx.x * blockDim.x + threadIdx.x;   // 4096 = [kt][t16][lane]
    int kt = t >> 9;
    int t16 = (t >> 5) & 15;
    int lane = t & 31;
    int gid = lane >> 2, tig = lane & 3;
    int eo = t16 >> 3;
    uint32_t w4[4];
#pragma unroll
    for (int w = 0; w < 4; ++w) {
        int m = t16 * 16 + gid + (w & 1) * 8;
        int c = m & 127;
        int kap0 = tig * 2 + (w >> 1) * 8;
        float v2[2];
#pragma unroll
        for (int h = 0; h < 2; ++h) {
            int k = kt * 32 + 2 * (kap0 + h) + eo;
            if (k == 0) v2[h] = 1.0f;
            else {
                int mm = (k * (2 * c + 1)) & 1023;
                v2[h] = 2.0f * cospif((float)mm * (1.0f / 512.0f));
            }
        }
        __half2 h2 = __floats2half2_rn(v2[0], v2[1]);
        w4[w] = *(uint32_t*)&h2;
    }
    *(uint4*)(g_A + (kt * 16 + t16) * 512 + lane * 16) =
        make_uint4(w4[0], w4[1], w4[2], w4[3]);
}

__device__ __forceinline__ void mma16816(float* c,
    uint32_t a0, uint32_t a1, uint32_t a2, uint32_t a3,
    uint32_t b0, uint32_t b1) {
    asm volatile(
        "mma.sync.aligned.m16n8k16.row.col.f32.f16.f16.f32 "
        "{%0,%1,%2,%3}, {%4,%5,%6,%7}, {%8,%9}, {%0,%1,%2,%3};"
        : "+f"(c[0]), "+f"(c[1]), "+f"(c[2]), "+f"(c[3])
        : "r"(a0), "r"(a1), "r"(a2), "r"(a3), "r"(b0), "r"(b1));
}

__global__ __launch_bounds__(THREADS, 1)
void idct_mma_kernel(const float* __restrict__ x, float* __restrict__ out) {
    extern __shared__ char sm[];
    const int tid  = threadIdx.x;
    const int lane = tid & 31;
    const int q    = lane & 3;
    const int frow = lane >> 2;
    const int wid  = tid >> 5;
    const int cg   = wid & 3;    // 32-channel group (0..3)
    const int pg   = wid >> 2;   // 32-px group (0..3)

    // B producer role: (px, parity, k-half); one STS.128 per chunk
    const int px   = tid & 127;
    const int par  = (tid >> 7) & 1;
    const int half = tid >> 8;
    const int g8   = px >> 3;
    const int r    = px & 7;
    const uint32_t psw = (uint32_t)((r & 4) << 2);
    const uint32_t po  = (uint32_t)(par * 8192 + g8 * 512) +
                         (((uint32_t)(r * 32 + half * 16)) ^ psw);
    // B consumer offset
    const uint32_t bco = (((uint32_t)(frow * 32)) +
                          (((uint32_t)(q * 8)) ^ ((uint32_t)((frow & 4) << 2))));

    int ti = blockIdx.x;

    // producer gmem base: global k offset = par + half*8
    const float* xpb = x + (size_t)(ti >> 7) * C_DIM * HW + (ti & 127) * 128
                         + px + (size_t)(par + half * 8) * HW;
    float v0[8], v1[8];       // chunk0 / chunk1 of current interval
#pragma unroll
    for (int j = 0; j < 4; ++j) {
        v0[j]     = xpb[(size_t)(2 * j) * HW];
        v0[4 + j] = xpb[(size_t)(16 + 2 * j) * HW];
        v1[j]     = xpb[(size_t)(32 + 2 * j) * HW];
        v1[4 + j] = xpb[(size_t)(48 + 2 * j) * HW];
    }

    // stage A once (64KB)
    {
        const uint4* src = (const uint4*)g_A;
        uint4* dst = (uint4*)sm;
#pragma unroll
        for (int i = 0; i < 8; ++i) dst[tid + 512 * i] = src[tid + 512 * i];
    }

    float acc[2][2][4][4];
#pragma unroll
    for (int a = 0; a < 2; a++)
#pragma unroll
        for (int e = 0; e < 2; e++)
#pragma unroll
            for (int b = 0; b < 4; b++)
#pragma unroll
                for (int j = 0; j < 4; j++) acc[a][e][b][j] = 0.0f;

    while (ti < NTILES) {
        const float* xnb = xpb;   // next-tile base (set at ss==3)

#pragma unroll 1
        for (int ss = 0; ss < 4; ++ss) {
            const uint32_t stg = SMB + (uint32_t)(ss & 1) * 32768;

            // cvt + STS both chunks: quad = pairs (v0,v1),(v4,v5),(v2,v3),(v6,v7)
            {
                __half2 a0 = __floats2half2_rn(v0[0], v0[1]);
                __half2 a1 = __floats2half2_rn(v0[4], v0[5]);
                __half2 a2 = __floats2half2_rn(v0[2], v0[3]);
                __half2 a3 = __floats2half2_rn(v0[6], v0[7]);
                *(uint4*)(sm + stg + po) =
                    make_uint4(*(uint32_t*)&a0, *(uint32_t*)&a1,
                               *(uint32_t*)&a2, *(uint32_t*)&a3);
                __half2 b0 = __floats2half2_rn(v1[0], v1[1]);
                __half2 b1 = __floats2half2_rn(v1[4], v1[5]);
                __half2 b2 = __floats2half2_rn(v1[2], v1[3]);
                __half2 b3 = __floats2half2_rn(v1[6], v1[7]);
                *(uint4*)(sm + stg + 16384 + po) =
                    make_uint4(*(uint32_t*)&b0, *(uint32_t*)&b1,
                               *(uint32_t*)&b2, *(uint32_t*)&b3);
            }

            // prefetch next interval (64 k) into v0/v1
            {
                const float* nb;
                if (ss < 3) {
                    nb = xpb + (size_t)(64 * (ss + 1)) * HW;
                } else {
                    int tn = (ti + GRID_P < NTILES) ? (ti + GRID_P) : ti;
                    xnb = x + (size_t)(tn >> 7) * C_DIM * HW + (tn & 127) * 128
                            + px + (size_t)(par + half * 8) * HW;
                    nb = xnb;
                }
#pragma unroll
                for (int j = 0; j < 4; ++j) {
                    v0[j]     = nb[(size_t)(2 * j) * HW];
                    v0[4 + j] = nb[(size_t)(16 + 2 * j) * HW];
                    v1[j]     = nb[(size_t)(32 + 2 * j) * HW];
                    v1[4 + j] = nb[(size_t)(48 + 2 * j) * HW];
                }
            }

            __syncthreads();

            // consume chunk 0 then chunk 1
#pragma unroll
            for (int c01 = 0; c01 < 2; ++c01) {
                uint2 Bh[2][4];
#pragma unroll
                for (int pr = 0; pr < 2; ++pr)
#pragma unroll
                    for (int nt = 0; nt < 4; ++nt) {
                        const char* bb = sm + stg + c01 * 16384 + pr * 8192 +
                                         (pg * 4 + nt) * 512 + bco;
                        Bh[pr][nt] = *(const uint2*)(bb);
                    }
                const int kt = ss * 2 + c01;
#pragma unroll
                for (int eo = 0; eo < 2; ++eo)
#pragma unroll
                    for (int mt = 0; mt < 2; ++mt) {
                        uint4 Aw = *(const uint4*)(sm +
                            (kt * 16 + eo * 8 + cg * 2 + mt) * 512 + lane * 16);
#pragma unroll
                        for (int nt = 0; nt < 4; ++nt)
                            mma16816(acc[mt][eo][nt], Aw.x, Aw.y, Aw.z, Aw.w,
                                     Bh[eo][nt].x, Bh[eo][nt].y);
                    }
            }
        }

        // ---- epilogue: parity combine in regs, sector-aligned STG ----
        {
            float* ob = out + (size_t)(ti >> 7) * C_DIM * HW + (ti & 127) * 128;
#pragma unroll
            for (int mt = 0; mt < 2; ++mt) {
                int c = cg * 32 + mt * 16 + frow;
#pragma unroll
                for (int nt = 0; nt < 4; ++nt) {
                    int pxo = pg * 32 + nt * 8 + q * 2;
                    float* E = acc[mt][0][nt];
                    float* O = acc[mt][1][nt];
                    *(float2*)&ob[(size_t)c * HW + pxo] =
                        make_float2(E[0] + O[0], E[1] + O[1]);
                    *(float2*)&ob[(size_t)(255 - c) * HW + pxo] =
                        make_float2(E[0] - O[0], E[1] - O[1]);
                    *(float2*)&ob[(size_t)(c + 8) * HW + pxo] =
                        make_float2(E[2] + O[2], E[3] + O[3]);
                    *(float2*)&ob[(size_t)(247 - c) * HW + pxo] =
                        make_float2(E[2] - O[2], E[3] - O[3]);
                    E[0] = E[1] = E[2] = E[3] = 0.0f;
                    O[0] = O[1] = O[2] = O[3] = 0.0f;
                }
            }
        }

        ti += GRID_P;
        xpb = xnb;
    }
}

extern "C" void kernel_launch(void* const* d_in, const int* in_sizes, int n_in,
                              void* d_out, int out_size) {
    const float* x = (const float*)d_in[0];
    float* out = (float*)d_out;

    cudaFuncSetAttribute(idct_mma_kernel,
                         cudaFuncAttributeMaxDynamicSharedMemorySize, SMEM_TOTAL);
    precompute_kernel<<<16, 256>>>();
    idct_mma_kernel<<<GRID_P, THREADS, SMEM_TOTAL>>>(x, out);
}